// round 3
// baseline (speedup 1.0000x reference)
#include <cuda_runtime.h>
#include <math.h>

#define Bsz 512
#define Tsz 512
#define Dsz 256
#define NC  4           // T-chunks per batch row
#define CROWS (Tsz/NC)  // 128 rows per chunk

// out = [p (512) | T_event (512x513) | L_t (512x256) | M_t (512)]
#define OFF_TE 512
#define OFF_L  (512 + 512*513)
#define OFF_M  (OFF_L + 512*256)

__device__ __align__(16) float g_G[Dsz*Dsz];          // W_Q^T @ W_K
__device__ __align__(16) float g_qpart[Bsz*NC*Dsz];   // pass-A partial sums
__device__ float g_cnt4[Bsz*NC];
__device__ float g_max4[Bsz*NC];
__device__ float g_tmax[Bsz];
__device__ __align__(16) float g_u[Bsz*Dsz];
__device__ __align__(16) float g_ypart[Bsz*NC*Dsz];   // pass-B partial pools
__device__ float g_m4[Bsz*NC], g_Z4[Bsz*NC], g_S4[Bsz*NC];

// ---------------- K0: G = W_Q^T @ W_K ----------------
__global__ void k_G(const float* __restrict__ WQ, const float* __restrict__ WK) {
    int d1b = blockIdx.x * 4, d2 = threadIdx.x;
    float a0 = 0.f, a1 = 0.f, a2 = 0.f, a3 = 0.f;
    #pragma unroll 4
    for (int e = 0; e < Dsz; e++) {
        float wk = __ldg(WK + e*Dsz + d2);
        a0 = fmaf(__ldg(WQ + e*Dsz + d1b + 0), wk, a0);
        a1 = fmaf(__ldg(WQ + e*Dsz + d1b + 1), wk, a1);
        a2 = fmaf(__ldg(WQ + e*Dsz + d1b + 2), wk, a2);
        a3 = fmaf(__ldg(WQ + e*Dsz + d1b + 3), wk, a3);
    }
    g_G[(d1b+0)*Dsz + d2] = a0;
    g_G[(d1b+1)*Dsz + d2] = a1;
    g_G[(d1b+2)*Dsz + d2] = a2;
    g_G[(d1b+3)*Dsz + d2] = a3;
}

// ---------------- K1: pass A partials (grid: NC x Bsz) ----------------
__global__ void __launch_bounds__(256)
k1a(const float* __restrict__ wf, const float* __restrict__ ts,
    const unsigned char* __restrict__ pad) {
    int c = blockIdx.x, b = blockIdx.y;
    int tid = threadIdx.x;
    int t0 = c * CROWS;

    __shared__ float s_valid[CROWS];
    __shared__ float s_rm[128], s_rc[128];
    __shared__ __align__(16) float4 s_acc[4][64];

    if (tid < CROWS) {
        float v = pad[b*Tsz + t0 + tid] ? 0.f : 1.f;
        s_valid[tid] = v;
        float tv = ts[b*Tsz + t0 + tid];
        s_rm[tid] = (v > 0.f) ? tv : -3.0e38f;
        s_rc[tid] = v;
    }
    __syncthreads();
    for (int s = 64; s > 0; s >>= 1) {
        if (tid < s) {
            s_rm[tid] = fmaxf(s_rm[tid], s_rm[tid+s]);
            s_rc[tid] += s_rc[tid+s];
        }
        __syncthreads();
    }

    int grp = tid >> 6, c4 = tid & 63;
    const float4* wf4 = (const float4*)(wf + (size_t)b*Tsz*Dsz + (size_t)t0*Dsz);
    float4 acc = make_float4(0.f,0.f,0.f,0.f);
    #pragma unroll 8
    for (int t = grp; t < CROWS; t += 4) {
        float4 v = wf4[t*64 + c4];
        float vm = s_valid[t];
        acc.x = fmaf(v.x, vm, acc.x);
        acc.y = fmaf(v.y, vm, acc.y);
        acc.z = fmaf(v.z, vm, acc.z);
        acc.w = fmaf(v.w, vm, acc.w);
    }
    s_acc[grp][c4] = acc;
    __syncthreads();
    int bc = b*NC + c;
    if (tid < 64) {
        float4 a = s_acc[0][tid], b1 = s_acc[1][tid], c2 = s_acc[2][tid], d = s_acc[3][tid];
        float4 r = make_float4(a.x+b1.x+c2.x+d.x, a.y+b1.y+c2.y+d.y,
                               a.z+b1.z+c2.z+d.z, a.w+b1.w+c2.w+d.w);
        ((float4*)(g_qpart + (size_t)bc*Dsz))[tid] = r;
    }
    if (tid == 0) { g_max4[bc] = s_rm[0]; g_cnt4[bc] = s_rc[0]; }
}

// ---------------- K2: reduce q, tmax; u = q @ G  (8 b per block) ----------------
__global__ void __launch_bounds__(256)
k_qu() {
    int b0 = blockIdx.x * 8, tid = threadIdx.x;
    __shared__ __align__(16) float s_q[8][Dsz];

    #pragma unroll
    for (int g = 0; g < 8; g++) {
        int b = b0 + g;
        float q = 0.f, cnt = 0.f, mx = -3.0e38f;
        #pragma unroll
        for (int c = 0; c < NC; c++) {
            q   += g_qpart[(size_t)(b*NC + c)*Dsz + tid];
            cnt += g_cnt4[b*NC + c];
            mx   = fmaxf(mx, g_max4[b*NC + c]);
        }
        s_q[g][tid] = q / fmaxf(cnt, 1.f);
        if (tid == 0) g_tmax[b] = mx;
    }
    __syncthreads();

    float a0=0.f,a1=0.f,a2=0.f,a3=0.f,a4=0.f,a5=0.f,a6=0.f,a7=0.f;
    const float* Gp = g_G + tid;
    #pragma unroll 8
    for (int i = 0; i < Dsz; i++) {
        float w = Gp[(size_t)i*Dsz];
        a0 = fmaf(s_q[0][i], w, a0); a1 = fmaf(s_q[1][i], w, a1);
        a2 = fmaf(s_q[2][i], w, a2); a3 = fmaf(s_q[3][i], w, a3);
        a4 = fmaf(s_q[4][i], w, a4); a5 = fmaf(s_q[5][i], w, a5);
        a6 = fmaf(s_q[6][i], w, a6); a7 = fmaf(s_q[7][i], w, a7);
    }
    g_u[(size_t)(b0+0)*Dsz+tid]=a0; g_u[(size_t)(b0+1)*Dsz+tid]=a1;
    g_u[(size_t)(b0+2)*Dsz+tid]=a2; g_u[(size_t)(b0+3)*Dsz+tid]=a3;
    g_u[(size_t)(b0+4)*Dsz+tid]=a4; g_u[(size_t)(b0+5)*Dsz+tid]=a5;
    g_u[(size_t)(b0+6)*Dsz+tid]=a6; g_u[(size_t)(b0+7)*Dsz+tid]=a7;
}

// ---------------- K3: pass B partials (grid: NC x Bsz) ----------------
__global__ void __launch_bounds__(256)
k3a(const float* __restrict__ wf, const float* __restrict__ ts,
    const unsigned char* __restrict__ pad) {
    int c = blockIdx.x, b = blockIdx.y;
    int tid = threadIdx.x;
    int warp = tid >> 5, lane = tid & 31;
    int t0 = c * CROWS;

    __shared__ float s_lam[CROWS];
    __shared__ float s_valid[CROWS];
    __shared__ float s_m[8], s_Z[8], s_S[8];
    __shared__ __align__(16) float s_yp[8*Dsz];

    float tmaxv = g_tmax[b];
    if (tid < CROWS) {
        float v = pad[b*Tsz + t0 + tid] ? 0.f : 1.f;
        float dt = fmaxf(tmaxv - ts[b*Tsz + t0 + tid], 0.f) * (1.f/86400.f);
        s_lam[tid] = __expf(-0.5f*dt) * v;
        s_valid[tid] = v;
    }
    __syncthreads();

    const float4* u4 = (const float4*)(g_u + (size_t)b*Dsz);
    float4 ua = u4[lane], ub = u4[lane + 32];
    const float4* wf4 = (const float4*)(wf + (size_t)b*Tsz*Dsz + (size_t)t0*Dsz);

    float m = -3.0e38f, Z = 0.f, S = 0.f;
    float4 ya = make_float4(0.f,0.f,0.f,0.f);
    float4 yb = make_float4(0.f,0.f,0.f,0.f);

    #pragma unroll 4
    for (int t = warp; t < CROWS; t += 8) {
        float4 wa = wf4[t*64 + lane];
        float4 wb = wf4[t*64 + 32 + lane];
        float d = wa.x*ua.x + wa.y*ua.y + wa.z*ua.z + wa.w*ua.w
                + wb.x*ub.x + wb.y*ub.y + wb.z*ub.z + wb.w*ub.w;
        #pragma unroll
        for (int o = 16; o > 0; o >>= 1) d += __shfl_xor_sync(0xffffffffu, d, o);
        if (s_valid[t] != 0.f) {
            float s  = d * 0.0625f;
            float nm = fmaxf(m, s);
            float sc = __expf(m - nm);
            float e  = __expf(s - nm);
            float g  = s_lam[t] * e;
            Z = Z*sc + e;
            S = S*sc + g;
            ya.x = fmaf(ya.x, sc, g*wa.x); ya.y = fmaf(ya.y, sc, g*wa.y);
            ya.z = fmaf(ya.z, sc, g*wa.z); ya.w = fmaf(ya.w, sc, g*wa.w);
            yb.x = fmaf(yb.x, sc, g*wb.x); yb.y = fmaf(yb.y, sc, g*wb.y);
            yb.z = fmaf(yb.z, sc, g*wb.z); yb.w = fmaf(yb.w, sc, g*wb.w);
            m = nm;
        }
    }

    if (lane == 0) s_m[warp] = m;
    __syncthreads();
    float M = s_m[0];
    #pragma unroll
    for (int w = 1; w < 8; w++) M = fmaxf(M, s_m[w]);
    float scw = __expf(m - M);
    if (lane == 0) { s_Z[warp] = Z*scw; s_S[warp] = S*scw; }
    float4* syp4 = (float4*)s_yp;
    syp4[warp*64 + lane]      = make_float4(ya.x*scw, ya.y*scw, ya.z*scw, ya.w*scw);
    syp4[warp*64 + 32 + lane] = make_float4(yb.x*scw, yb.y*scw, yb.z*scw, yb.w*scw);
    __syncthreads();

    int bc = b*NC + c;
    {
        float yv = 0.f;
        #pragma unroll
        for (int w = 0; w < 8; w++) yv += s_yp[w*Dsz + tid];
        g_ypart[(size_t)bc*Dsz + tid] = yv;
    }
    if (tid == 0) {
        float Zt = 0.f, St = 0.f;
        #pragma unroll
        for (int w = 0; w < 8; w++) { Zt += s_Z[w]; St += s_S[w]; }
        g_m4[bc] = M; g_Z4[bc] = Zt; g_S4[bc] = St;
    }
}

// ---------------- K4: combine y + L = y@WV^T + epilogue (4 b per block) ----------------
__global__ void __launch_bounds__(256)
k4(const float* __restrict__ WV, const float* __restrict__ prevL,
   const float* __restrict__ prevM, const float* __restrict__ clsw,
   const float* __restrict__ clsb, float* __restrict__ out) {
    int b0 = blockIdx.x * 4, tid = threadIdx.x;
    int warp = tid >> 5, lane = tid & 31;
    __shared__ __align__(16) float s_yf[4][Dsz];
    __shared__ __align__(16) float s_L[4][Dsz];
    __shared__ float s_w1[8], s_w2[8];

    #pragma unroll
    for (int g = 0; g < 4; g++) {
        int b = b0 + g;
        float m0 = g_m4[b*NC+0], m1 = g_m4[b*NC+1], m2 = g_m4[b*NC+2], m3 = g_m4[b*NC+3];
        float M = fmaxf(fmaxf(m0, m1), fmaxf(m2, m3));
        float c0 = __expf(m0 - M), c1 = __expf(m1 - M), c2 = __expf(m2 - M), c3 = __expf(m3 - M);
        float Zt = g_Z4[b*NC+0]*c0 + g_Z4[b*NC+1]*c1 + g_Z4[b*NC+2]*c2 + g_Z4[b*NC+3]*c3;
        float St = g_S4[b*NC+0]*c0 + g_S4[b*NC+1]*c1 + g_S4[b*NC+2]*c2 + g_S4[b*NC+3]*c3;
        float yv = g_ypart[(size_t)(b*NC+0)*Dsz+tid]*c0 + g_ypart[(size_t)(b*NC+1)*Dsz+tid]*c1
                 + g_ypart[(size_t)(b*NC+2)*Dsz+tid]*c2 + g_ypart[(size_t)(b*NC+3)*Dsz+tid]*c3;
        float denom = St + 1e-8f*Zt;
        float inv = denom > 0.f ? 1.f/denom : 0.f;
        s_yf[g][tid] = yv * inv;
    }
    __syncthreads();

    // GEMM: warp-per-row, lanes over d (coalesced), 4 b reuse each WV row
    {
        const float4* y0 = (const float4*)s_yf[0];
        const float4* y1 = (const float4*)s_yf[1];
        const float4* y2 = (const float4*)s_yf[2];
        const float4* y3 = (const float4*)s_yf[3];
        float4 y0A = y0[lane*2], y0B = y0[lane*2+1];
        float4 y1A = y1[lane*2], y1B = y1[lane*2+1];
        float4 y2A = y2[lane*2], y2B = y2[lane*2+1];
        float4 y3A = y3[lane*2], y3B = y3[lane*2+1];
        #pragma unroll 4
        for (int i = 0; i < 32; i++) {
            int e = warp*32 + i;
            const float4* wr = (const float4*)(WV + (size_t)e*Dsz);
            float4 wA = wr[lane*2], wB = wr[lane*2+1];
            float d0 = wA.x*y0A.x + wA.y*y0A.y + wA.z*y0A.z + wA.w*y0A.w
                     + wB.x*y0B.x + wB.y*y0B.y + wB.z*y0B.z + wB.w*y0B.w;
            float d1 = wA.x*y1A.x + wA.y*y1A.y + wA.z*y1A.z + wA.w*y1A.w
                     + wB.x*y1B.x + wB.y*y1B.y + wB.z*y1B.z + wB.w*y1B.w;
            float d2 = wA.x*y2A.x + wA.y*y2A.y + wA.z*y2A.z + wA.w*y2A.w
                     + wB.x*y2B.x + wB.y*y2B.y + wB.z*y2B.z + wB.w*y2B.w;
            float d3 = wA.x*y3A.x + wA.y*y3A.y + wA.z*y3A.z + wA.w*y3A.w
                     + wB.x*y3B.x + wB.y*y3B.y + wB.z*y3B.z + wB.w*y3B.w;
            #pragma unroll
            for (int o = 16; o > 0; o >>= 1) {
                d0 += __shfl_xor_sync(0xffffffffu, d0, o);
                d1 += __shfl_xor_sync(0xffffffffu, d1, o);
                d2 += __shfl_xor_sync(0xffffffffu, d2, o);
                d3 += __shfl_xor_sync(0xffffffffu, d3, o);
            }
            if (lane == 0) { s_L[0][e]=d0; s_L[1][e]=d1; s_L[2][e]=d2; s_L[3][e]=d3; }
        }
    }
    __syncthreads();

    float cw1 = clsw[tid], cw2 = clsw[Dsz + tid];
    #pragma unroll
    for (int g = 0; g < 4; g++) {
        int b = b0 + g;
        float L  = s_L[g][tid];
        float dl = L - prevL[(size_t)b*Dsz + tid];
        float r1 = dl*dl;
        float r2 = fmaf(L, cw1, dl*cw2);
        #pragma unroll
        for (int o = 16; o > 0; o >>= 1) {
            r1 += __shfl_xor_sync(0xffffffffu, r1, o);
            r2 += __shfl_xor_sync(0xffffffffu, r2, o);
        }
        if (lane == 0) { s_w1[warp] = r1; s_w2[warp] = r2; }
        __syncthreads();
        size_t te = (size_t)OFF_TE + (size_t)b*513;
        out[te + tid]       = L;
        out[te + 256 + tid] = dl;
        out[OFF_L + (size_t)b*Dsz + tid] = L;
        if (tid == 0) {
            float R1 = 0.f, R2 = 0.f;
            #pragma unroll
            for (int w = 0; w < 8; w++) { R1 += s_w1[w]; R2 += s_w2[w]; }
            float Mt = 0.9f*prevM[b] + 0.1f*sqrtf(R1);
            out[OFF_M + b] = Mt;
            out[te + 512]  = Mt;
            out[b] = R2 + Mt*clsw[2*Dsz] + clsb[0];
        }
        __syncthreads();
    }
}

extern "C" void kernel_launch(void* const* d_in, const int* in_sizes, int n_in,
                              void* d_out, int out_size) {
    const float*         wf    = (const float*)d_in[0];
    const float*         ts    = (const float*)d_in[1];
    const float*         prevL = (const float*)d_in[2];
    const float*         prevM = (const float*)d_in[3];
    const unsigned char* pad   = (const unsigned char*)d_in[4];
    const float*         WQ    = (const float*)d_in[5];
    const float*         WK    = (const float*)d_in[6];
    const float*         WV    = (const float*)d_in[7];
    const float*         clsw  = (const float*)d_in[8];
    const float*         clsb  = (const float*)d_in[9];
    float* out = (float*)d_out;

    k_G <<<Dsz/4, 256>>>(WQ, WK);
    k1a <<<dim3(NC, Bsz), 256>>>(wf, ts, pad);
    k_qu<<<Bsz/8, 256>>>();
    k3a <<<dim3(NC, Bsz), 256>>>(wf, ts, pad);
    k4  <<<Bsz/4, 256>>>(WV, prevL, prevM, clsw, clsb, out);
}

// round 4
// speedup vs baseline: 1.2954x; 1.2954x over previous
#include <cuda_runtime.h>
#include <math.h>

#define Bsz 512
#define Tsz 512
#define Dsz 256
#define NC  4           // T-chunks per batch row
#define CROWS (Tsz/NC)  // 128 rows per chunk

// out = [p (512) | T_event (512x513) | L_t (512x256) | M_t (512)]
#define OFF_TE 512
#define OFF_L  (512 + 512*513)
#define OFF_M  (OFF_L + 512*256)

__device__ __align__(16) float g_qpart[Bsz*NC*Dsz];   // pass-A partial sums
__device__ float g_cnt4[Bsz*NC];
__device__ float g_max4[Bsz*NC];
__device__ float g_tmax[Bsz];
__device__ __align__(16) float g_u[Bsz*Dsz];
__device__ __align__(16) float g_ypart[Bsz*NC*Dsz];   // pass-B partial pools
__device__ float g_m4[Bsz*NC], g_Z4[Bsz*NC], g_S4[Bsz*NC];

// ---------------- K1: pass A partials (grid: NC x Bsz) ----------------
__global__ void __launch_bounds__(256)
k1a(const float* __restrict__ wf, const float* __restrict__ ts,
    const unsigned char* __restrict__ pad) {
    int c = blockIdx.x, b = blockIdx.y;
    int tid = threadIdx.x;
    int warp = tid >> 5, lane = tid & 31;
    int t0 = c * CROWS;

    __shared__ float s_valid[CROWS];
    __shared__ float s_rm[CROWS], s_rc[CROWS];
    __shared__ __align__(16) float s_acc[8*Dsz];

    if (tid < CROWS) {
        float v = pad[b*Tsz + t0 + tid] ? 0.f : 1.f;
        s_valid[tid] = v;
        float tv = ts[b*Tsz + t0 + tid];
        s_rm[tid] = (v > 0.f) ? tv : -3.0e38f;
        s_rc[tid] = v;
    }
    __syncthreads();
    for (int s = 64; s > 0; s >>= 1) {
        if (tid < s) {
            s_rm[tid] = fmaxf(s_rm[tid], s_rm[tid+s]);
            s_rc[tid] += s_rc[tid+s];
        }
        __syncthreads();
    }

    const float4* wf4 = (const float4*)(wf + (size_t)b*Tsz*Dsz + (size_t)t0*Dsz);
    float4 A = make_float4(0.f,0.f,0.f,0.f);
    float4 B = make_float4(0.f,0.f,0.f,0.f);
    #pragma unroll 4
    for (int t = warp*2; t < CROWS; t += 16) {
        float4 wa0 = wf4[t*64 + lane];
        float4 wb0 = wf4[t*64 + 32 + lane];
        float4 wa1 = wf4[(t+1)*64 + lane];
        float4 wb1 = wf4[(t+1)*64 + 32 + lane];
        float v0 = s_valid[t], v1 = s_valid[t+1];
        A.x = fmaf(wa0.x, v0, fmaf(wa1.x, v1, A.x));
        A.y = fmaf(wa0.y, v0, fmaf(wa1.y, v1, A.y));
        A.z = fmaf(wa0.z, v0, fmaf(wa1.z, v1, A.z));
        A.w = fmaf(wa0.w, v0, fmaf(wa1.w, v1, A.w));
        B.x = fmaf(wb0.x, v0, fmaf(wb1.x, v1, B.x));
        B.y = fmaf(wb0.y, v0, fmaf(wb1.y, v1, B.y));
        B.z = fmaf(wb0.z, v0, fmaf(wb1.z, v1, B.z));
        B.w = fmaf(wb0.w, v0, fmaf(wb1.w, v1, B.w));
    }
    float4* sa4 = (float4*)s_acc;
    sa4[warp*64 + lane]      = A;
    sa4[warp*64 + 32 + lane] = B;
    __syncthreads();

    int bc = b*NC + c;
    {
        float q = 0.f;
        #pragma unroll
        for (int w = 0; w < 8; w++) q += s_acc[w*Dsz + tid];
        g_qpart[(size_t)bc*Dsz + tid] = q;
    }
    if (tid == 0) { g_max4[bc] = s_rm[0]; g_cnt4[bc] = s_rc[0]; }
}

// ---------------- K2: reduce q, tmax; Q=q@WQ^T; u=Q@WK (8 b per block) ----------------
__global__ void __launch_bounds__(256)
k_qu(const float* __restrict__ WQ, const float* __restrict__ WK) {
    int b0 = blockIdx.x * 8, tid = threadIdx.x;
    int warp = tid >> 5, lane = tid & 31;
    __shared__ __align__(16) float s_q[8][Dsz];
    __shared__ __align__(16) float s_Q[8][Dsz];

    #pragma unroll
    for (int g = 0; g < 8; g++) {
        int b = b0 + g;
        float q = 0.f, cnt = 0.f, mx = -3.0e38f;
        #pragma unroll
        for (int c = 0; c < NC; c++) {
            q   += g_qpart[(size_t)(b*NC + c)*Dsz + tid];
            cnt += g_cnt4[b*NC + c];
            mx   = fmaxf(mx, g_max4[b*NC + c]);
        }
        s_q[g][tid] = q / fmaxf(cnt, 1.f);
        if (tid == 0) g_tmax[b] = mx;
    }
    __syncthreads();

    // Stage 1: Q[g][e] = sum_d q[g][d]*WQ[e,d] — warp per row e, lanes over d
    #pragma unroll 2
    for (int r = 0; r < 32; r++) {
        int e = warp*32 + r;
        const float4* wr = (const float4*)(WQ + (size_t)e*Dsz);
        float4 wA = wr[lane*2], wB = wr[lane*2 + 1];
        float d[8];
        #pragma unroll
        for (int g = 0; g < 8; g++) {
            const float4* q4 = (const float4*)s_q[g];
            float4 qA = q4[lane*2], qB = q4[lane*2 + 1];
            d[g] = wA.x*qA.x + wA.y*qA.y + wA.z*qA.z + wA.w*qA.w
                 + wB.x*qB.x + wB.y*qB.y + wB.z*qB.z + wB.w*qB.w;
        }
        #pragma unroll
        for (int o = 16; o > 0; o >>= 1) {
            #pragma unroll
            for (int g = 0; g < 8; g++) d[g] += __shfl_xor_sync(0xffffffffu, d[g], o);
        }
        if (lane == 0) {
            #pragma unroll
            for (int g = 0; g < 8; g++) s_Q[g][e] = d[g];
        }
    }
    __syncthreads();

    // Stage 2: u[g][d2] = sum_e Q[g][e]*WK[e,d2] — threads over d2 (coalesced)
    {
        float a[8];
        #pragma unroll
        for (int g = 0; g < 8; g++) a[g] = 0.f;
        const float* Wp = WK + tid;
        #pragma unroll 4
        for (int e = 0; e < Dsz; e++) {
            float w = __ldg(Wp + (size_t)e*Dsz);
            #pragma unroll
            for (int g = 0; g < 8; g++) a[g] = fmaf(s_Q[g][e], w, a[g]);
        }
        #pragma unroll
        for (int g = 0; g < 8; g++) g_u[(size_t)(b0+g)*Dsz + tid] = a[g];
    }
}

// ---------------- K3: pass B partials (grid: NC x Bsz) ----------------
__global__ void __launch_bounds__(256)
k3a(const float* __restrict__ wf, const float* __restrict__ ts,
    const unsigned char* __restrict__ pad) {
    int c = blockIdx.x, b = blockIdx.y;
    int tid = threadIdx.x;
    int warp = tid >> 5, lane = tid & 31;
    int t0 = c * CROWS;

    __shared__ float s_lam[CROWS];
    __shared__ float s_valid[CROWS];
    __shared__ float s_m[8], s_Z[8], s_S[8];
    __shared__ __align__(16) float s_yp[8*Dsz];

    float tmaxv = g_tmax[b];
    if (tid < CROWS) {
        float v = pad[b*Tsz + t0 + tid] ? 0.f : 1.f;
        float dt = fmaxf(tmaxv - ts[b*Tsz + t0 + tid], 0.f) * (1.f/86400.f);
        s_lam[tid] = __expf(-0.5f*dt) * v;
        s_valid[tid] = v;
    }
    __syncthreads();

    const float4* u4 = (const float4*)(g_u + (size_t)b*Dsz);
    float4 ua = u4[lane], ub = u4[lane + 32];
    const float4* wf4 = (const float4*)(wf + (size_t)b*Tsz*Dsz + (size_t)t0*Dsz);

    float m = -3.0e38f, Z = 0.f, S = 0.f;
    float4 ya = make_float4(0.f,0.f,0.f,0.f);
    float4 yb = make_float4(0.f,0.f,0.f,0.f);

    #pragma unroll 2
    for (int t = warp*2; t < CROWS; t += 16) {
        float4 wa0 = wf4[t*64 + lane];
        float4 wb0 = wf4[t*64 + 32 + lane];
        float4 wa1 = wf4[(t+1)*64 + lane];
        float4 wb1 = wf4[(t+1)*64 + 32 + lane];
        float d0 = wa0.x*ua.x + wa0.y*ua.y + wa0.z*ua.z + wa0.w*ua.w
                 + wb0.x*ub.x + wb0.y*ub.y + wb0.z*ub.z + wb0.w*ub.w;
        float d1 = wa1.x*ua.x + wa1.y*ua.y + wa1.z*ua.z + wa1.w*ua.w
                 + wb1.x*ub.x + wb1.y*ub.y + wb1.z*ub.z + wb1.w*ub.w;
        #pragma unroll
        for (int o = 16; o > 0; o >>= 1) {
            d0 += __shfl_xor_sync(0xffffffffu, d0, o);
            d1 += __shfl_xor_sync(0xffffffffu, d1, o);
        }
        if (s_valid[t] != 0.f) {
            float s  = d0 * 0.0625f;
            float nm = fmaxf(m, s);
            float sc = __expf(m - nm);
            float e  = __expf(s - nm);
            float g  = s_lam[t] * e;
            Z = Z*sc + e;
            S = S*sc + g;
            ya.x = fmaf(ya.x, sc, g*wa0.x); ya.y = fmaf(ya.y, sc, g*wa0.y);
            ya.z = fmaf(ya.z, sc, g*wa0.z); ya.w = fmaf(ya.w, sc, g*wa0.w);
            yb.x = fmaf(yb.x, sc, g*wb0.x); yb.y = fmaf(yb.y, sc, g*wb0.y);
            yb.z = fmaf(yb.z, sc, g*wb0.z); yb.w = fmaf(yb.w, sc, g*wb0.w);
            m = nm;
        }
        if (s_valid[t+1] != 0.f) {
            float s  = d1 * 0.0625f;
            float nm = fmaxf(m, s);
            float sc = __expf(m - nm);
            float e  = __expf(s - nm);
            float g  = s_lam[t+1] * e;
            Z = Z*sc + e;
            S = S*sc + g;
            ya.x = fmaf(ya.x, sc, g*wa1.x); ya.y = fmaf(ya.y, sc, g*wa1.y);
            ya.z = fmaf(ya.z, sc, g*wa1.z); ya.w = fmaf(ya.w, sc, g*wa1.w);
            yb.x = fmaf(yb.x, sc, g*wb1.x); yb.y = fmaf(yb.y, sc, g*wb1.y);
            yb.z = fmaf(yb.z, sc, g*wb1.z); yb.w = fmaf(yb.w, sc, g*wb1.w);
            m = nm;
        }
    }

    if (lane == 0) s_m[warp] = m;
    __syncthreads();
    float M = s_m[0];
    #pragma unroll
    for (int w = 1; w < 8; w++) M = fmaxf(M, s_m[w]);
    float scw = __expf(m - M);
    if (lane == 0) { s_Z[warp] = Z*scw; s_S[warp] = S*scw; }
    float4* syp4 = (float4*)s_yp;
    syp4[warp*64 + lane]      = make_float4(ya.x*scw, ya.y*scw, ya.z*scw, ya.w*scw);
    syp4[warp*64 + 32 + lane] = make_float4(yb.x*scw, yb.y*scw, yb.z*scw, yb.w*scw);
    __syncthreads();

    int bc = b*NC + c;
    {
        float yv = 0.f;
        #pragma unroll
        for (int w = 0; w < 8; w++) yv += s_yp[w*Dsz + tid];
        g_ypart[(size_t)bc*Dsz + tid] = yv;
    }
    if (tid == 0) {
        float Zt = 0.f, St = 0.f;
        #pragma unroll
        for (int w = 0; w < 8; w++) { Zt += s_Z[w]; St += s_S[w]; }
        g_m4[bc] = M; g_Z4[bc] = Zt; g_S4[bc] = St;
    }
}

// ---------------- K4: combine y + L = y@WV^T + epilogue (4 b per block) ----------------
__global__ void __launch_bounds__(256)
k4(const float* __restrict__ WV, const float* __restrict__ prevL,
   const float* __restrict__ prevM, const float* __restrict__ clsw,
   const float* __restrict__ clsb, float* __restrict__ out) {
    int b0 = blockIdx.x * 4, tid = threadIdx.x;
    int warp = tid >> 5, lane = tid & 31;
    __shared__ __align__(16) float s_yf[4][Dsz];
    __shared__ __align__(16) float s_L[4][Dsz];
    __shared__ float s_w1[8], s_w2[8];

    #pragma unroll
    for (int g = 0; g < 4; g++) {
        int b = b0 + g;
        float m0 = g_m4[b*NC+0], m1 = g_m4[b*NC+1], m2 = g_m4[b*NC+2], m3 = g_m4[b*NC+3];
        float M = fmaxf(fmaxf(m0, m1), fmaxf(m2, m3));
        float c0 = __expf(m0 - M), c1 = __expf(m1 - M), c2 = __expf(m2 - M), c3 = __expf(m3 - M);
        float Zt = g_Z4[b*NC+0]*c0 + g_Z4[b*NC+1]*c1 + g_Z4[b*NC+2]*c2 + g_Z4[b*NC+3]*c3;
        float St = g_S4[b*NC+0]*c0 + g_S4[b*NC+1]*c1 + g_S4[b*NC+2]*c2 + g_S4[b*NC+3]*c3;
        float yv = g_ypart[(size_t)(b*NC+0)*Dsz+tid]*c0 + g_ypart[(size_t)(b*NC+1)*Dsz+tid]*c1
                 + g_ypart[(size_t)(b*NC+2)*Dsz+tid]*c2 + g_ypart[(size_t)(b*NC+3)*Dsz+tid]*c3;
        float denom = St + 1e-8f*Zt;
        float inv = denom > 0.f ? 1.f/denom : 0.f;
        s_yf[g][tid] = yv * inv;
    }
    __syncthreads();

    {
        const float4* y0 = (const float4*)s_yf[0];
        const float4* y1 = (const float4*)s_yf[1];
        const float4* y2 = (const float4*)s_yf[2];
        const float4* y3 = (const float4*)s_yf[3];
        float4 y0A = y0[lane*2], y0B = y0[lane*2+1];
        float4 y1A = y1[lane*2], y1B = y1[lane*2+1];
        float4 y2A = y2[lane*2], y2B = y2[lane*2+1];
        float4 y3A = y3[lane*2], y3B = y3[lane*2+1];
        #pragma unroll 4
        for (int i = 0; i < 32; i++) {
            int e = warp*32 + i;
            const float4* wr = (const float4*)(WV + (size_t)e*Dsz);
            float4 wA = wr[lane*2], wB = wr[lane*2+1];
            float d0 = wA.x*y0A.x + wA.y*y0A.y + wA.z*y0A.z + wA.w*y0A.w
                     + wB.x*y0B.x + wB.y*y0B.y + wB.z*y0B.z + wB.w*y0B.w;
            float d1 = wA.x*y1A.x + wA.y*y1A.y + wA.z*y1A.z + wA.w*y1A.w
                     + wB.x*y1B.x + wB.y*y1B.y + wB.z*y1B.z + wB.w*y1B.w;
            float d2 = wA.x*y2A.x + wA.y*y2A.y + wA.z*y2A.z + wA.w*y2A.w
                     + wB.x*y2B.x + wB.y*y2B.y + wB.z*y2B.z + wB.w*y2B.w;
            float d3 = wA.x*y3A.x + wA.y*y3A.y + wA.z*y3A.z + wA.w*y3A.w
                     + wB.x*y3B.x + wB.y*y3B.y + wB.z*y3B.z + wB.w*y3B.w;
            #pragma unroll
            for (int o = 16; o > 0; o >>= 1) {
                d0 += __shfl_xor_sync(0xffffffffu, d0, o);
                d1 += __shfl_xor_sync(0xffffffffu, d1, o);
                d2 += __shfl_xor_sync(0xffffffffu, d2, o);
                d3 += __shfl_xor_sync(0xffffffffu, d3, o);
            }
            if (lane == 0) { s_L[0][e]=d0; s_L[1][e]=d1; s_L[2][e]=d2; s_L[3][e]=d3; }
        }
    }
    __syncthreads();

    float cw1 = clsw[tid], cw2 = clsw[Dsz + tid];
    #pragma unroll
    for (int g = 0; g < 4; g++) {
        int b = b0 + g;
        float L  = s_L[g][tid];
        float dl = L - prevL[(size_t)b*Dsz + tid];
        float r1 = dl*dl;
        float r2 = fmaf(L, cw1, dl*cw2);
        #pragma unroll
        for (int o = 16; o > 0; o >>= 1) {
            r1 += __shfl_xor_sync(0xffffffffu, r1, o);
            r2 += __shfl_xor_sync(0xffffffffu, r2, o);
        }
        if (lane == 0) { s_w1[warp] = r1; s_w2[warp] = r2; }
        __syncthreads();
        size_t te = (size_t)OFF_TE + (size_t)b*513;
        out[te + tid]       = L;
        out[te + 256 + tid] = dl;
        out[OFF_L + (size_t)b*Dsz + tid] = L;
        if (tid == 0) {
            float R1 = 0.f, R2 = 0.f;
            #pragma unroll
            for (int w = 0; w < 8; w++) { R1 += s_w1[w]; R2 += s_w2[w]; }
            float Mt = 0.9f*prevM[b] + 0.1f*sqrtf(R1);
            out[OFF_M + b] = Mt;
            out[te + 512]  = Mt;
            out[b] = R2 + Mt*clsw[2*Dsz] + clsb[0];
        }
        __syncthreads();
    }
}

extern "C" void kernel_launch(void* const* d_in, const int* in_sizes, int n_in,
                              void* d_out, int out_size) {
    const float*         wf    = (const float*)d_in[0];
    const float*         ts    = (const float*)d_in[1];
    const float*         prevL = (const float*)d_in[2];
    const float*         prevM = (const float*)d_in[3];
    const unsigned char* pad   = (const unsigned char*)d_in[4];
    const float*         WQ    = (const float*)d_in[5];
    const float*         WK    = (const float*)d_in[6];
    const float*         WV    = (const float*)d_in[7];
    const float*         clsw  = (const float*)d_in[8];
    const float*         clsb  = (const float*)d_in[9];
    float* out = (float*)d_out;

    k1a <<<dim3(NC, Bsz), 256>>>(wf, ts, pad);
    k_qu<<<Bsz/8, 256>>>(WQ, WK);
    k3a <<<dim3(NC, Bsz), 256>>>(wf, ts, pad);
    k4  <<<Bsz/4, 256>>>(WV, prevL, prevM, clsw, clsb, out);
}

// round 5
// speedup vs baseline: 1.5077x; 1.1639x over previous
#include <cuda_runtime.h>
#include <math.h>

#define Bsz 512
#define Tsz 512
#define Dsz 256
#define NC  4           // T-chunks per batch row
#define CROWS (Tsz/NC)  // 128 rows per chunk

// out = [p (512) | T_event (512x513) | L_t (512x256) | M_t (512)]
#define OFF_TE 512
#define OFF_L  (512 + 512*513)
#define OFF_M  (OFF_L + 512*256)

__device__ __align__(16) float g_qpart[Bsz*NC*Dsz];   // pass-A partial sums
__device__ float g_cnt4[Bsz*NC];
__device__ float g_max4[Bsz*NC];
__device__ float g_tmax[Bsz];
__device__ __align__(16) float g_u[Bsz*Dsz];
__device__ __align__(16) float g_ypart[Bsz*NC*Dsz];   // pass-B partial pools
__device__ float g_m4[Bsz*NC], g_Z4[Bsz*NC], g_S4[Bsz*NC];

// ---------------- K1: pass A partials (grid: NC x Bsz) ----------------
__global__ void __launch_bounds__(256)
k1a(const float* __restrict__ wf, const float* __restrict__ ts,
    const unsigned char* __restrict__ pad) {
    int c = blockIdx.x, b = blockIdx.y;
    int tid = threadIdx.x;
    int warp = tid >> 5, lane = tid & 31;
    int t0 = c * CROWS;

    __shared__ float s_valid[CROWS];
    __shared__ float s_rm[CROWS], s_rc[CROWS];
    __shared__ __align__(16) float s_acc[8*Dsz];

    if (tid < CROWS) {
        float v = pad[b*Tsz + t0 + tid] ? 0.f : 1.f;
        s_valid[tid] = v;
        float tv = ts[b*Tsz + t0 + tid];
        s_rm[tid] = (v > 0.f) ? tv : -3.0e38f;
        s_rc[tid] = v;
    }
    __syncthreads();
    for (int s = 64; s > 0; s >>= 1) {
        if (tid < s) {
            s_rm[tid] = fmaxf(s_rm[tid], s_rm[tid+s]);
            s_rc[tid] += s_rc[tid+s];
        }
        __syncthreads();
    }

    const float4* wf4 = (const float4*)(wf + (size_t)b*Tsz*Dsz + (size_t)t0*Dsz);
    float4 A = make_float4(0.f,0.f,0.f,0.f);
    float4 B = make_float4(0.f,0.f,0.f,0.f);
    #pragma unroll 4
    for (int t = warp*2; t < CROWS; t += 16) {
        float4 wa0 = wf4[t*64 + lane];
        float4 wb0 = wf4[t*64 + 32 + lane];
        float4 wa1 = wf4[(t+1)*64 + lane];
        float4 wb1 = wf4[(t+1)*64 + 32 + lane];
        float v0 = s_valid[t], v1 = s_valid[t+1];
        A.x = fmaf(wa0.x, v0, fmaf(wa1.x, v1, A.x));
        A.y = fmaf(wa0.y, v0, fmaf(wa1.y, v1, A.y));
        A.z = fmaf(wa0.z, v0, fmaf(wa1.z, v1, A.z));
        A.w = fmaf(wa0.w, v0, fmaf(wa1.w, v1, A.w));
        B.x = fmaf(wb0.x, v0, fmaf(wb1.x, v1, B.x));
        B.y = fmaf(wb0.y, v0, fmaf(wb1.y, v1, B.y));
        B.z = fmaf(wb0.z, v0, fmaf(wb1.z, v1, B.z));
        B.w = fmaf(wb0.w, v0, fmaf(wb1.w, v1, B.w));
    }
    float4* sa4 = (float4*)s_acc;
    sa4[warp*64 + lane]      = A;
    sa4[warp*64 + 32 + lane] = B;
    __syncthreads();

    int bc = b*NC + c;
    {
        float q = 0.f;
        #pragma unroll
        for (int w = 0; w < 8; w++) q += s_acc[w*Dsz + tid];
        g_qpart[(size_t)bc*Dsz + tid] = q;
    }
    if (tid == 0) { g_max4[bc] = s_rm[0]; g_cnt4[bc] = s_rc[0]; }
}

// ---------------- K2: reduce q, tmax; Q=q@WQ^T; u=Q@WK (4 b per block, grid 128) ----------------
__global__ void __launch_bounds__(256)
k_qu(const float* __restrict__ WQ, const float* __restrict__ WK) {
    int b0 = blockIdx.x * 4, tid = threadIdx.x;
    int warp = tid >> 5, lane = tid & 31;
    __shared__ __align__(16) float s_q[4][Dsz];
    __shared__ __align__(16) float s_Q[4][Dsz];

    #pragma unroll
    for (int g = 0; g < 4; g++) {
        int b = b0 + g;
        float q = 0.f, cnt = 0.f, mx = -3.0e38f;
        #pragma unroll
        for (int c = 0; c < NC; c++) {
            q   += g_qpart[(size_t)(b*NC + c)*Dsz + tid];
            cnt += g_cnt4[b*NC + c];
            mx   = fmaxf(mx, g_max4[b*NC + c]);
        }
        s_q[g][tid] = q / fmaxf(cnt, 1.f);
        if (tid == 0) g_tmax[b] = mx;
    }
    __syncthreads();

    // Stage 1: Q[g][e] = sum_d q[g][d]*WQ[e,d] — warp per row e, 2 rows in flight
    {
        float4 qA[4], qB[4];
        #pragma unroll
        for (int g = 0; g < 4; g++) {
            const float4* q4 = (const float4*)s_q[g];
            qA[g] = q4[lane*2]; qB[g] = q4[lane*2 + 1];
        }
        #pragma unroll 2
        for (int i = 0; i < 32; i += 2) {
            int e0 = warp*32 + i, e1 = e0 + 1;
            const float4* wr0 = (const float4*)(WQ + (size_t)e0*Dsz);
            const float4* wr1 = (const float4*)(WQ + (size_t)e1*Dsz);
            float4 w0A = wr0[lane*2], w0B = wr0[lane*2 + 1];
            float4 w1A = wr1[lane*2], w1B = wr1[lane*2 + 1];
            float d[8];
            #pragma unroll
            for (int g = 0; g < 4; g++) {
                d[g]   = w0A.x*qA[g].x + w0A.y*qA[g].y + w0A.z*qA[g].z + w0A.w*qA[g].w
                       + w0B.x*qB[g].x + w0B.y*qB[g].y + w0B.z*qB[g].z + w0B.w*qB[g].w;
                d[4+g] = w1A.x*qA[g].x + w1A.y*qA[g].y + w1A.z*qA[g].z + w1A.w*qA[g].w
                       + w1B.x*qB[g].x + w1B.y*qB[g].y + w1B.z*qB[g].z + w1B.w*qB[g].w;
            }
            #pragma unroll
            for (int o = 16; o > 0; o >>= 1) {
                #pragma unroll
                for (int k = 0; k < 8; k++) d[k] += __shfl_xor_sync(0xffffffffu, d[k], o);
            }
            if (lane == 0) {
                #pragma unroll
                for (int g = 0; g < 4; g++) { s_Q[g][e0] = d[g]; s_Q[g][e1] = d[4+g]; }
            }
        }
    }
    __syncthreads();

    // Stage 2: u[g][d2] = sum_e Q[g][e]*WK[e,d2] — threads over d2 (coalesced)
    {
        float a[4] = {0.f, 0.f, 0.f, 0.f};
        const float* Wp = WK + tid;
        #pragma unroll 8
        for (int e = 0; e < Dsz; e++) {
            float w = __ldg(Wp + (size_t)e*Dsz);
            #pragma unroll
            for (int g = 0; g < 4; g++) a[g] = fmaf(s_Q[g][e], w, a[g]);
        }
        #pragma unroll
        for (int g = 0; g < 4; g++) g_u[(size_t)(b0+g)*Dsz + tid] = a[g];
    }
}

// ---------------- K3: pass B partials (grid: NC x Bsz) ----------------
__global__ void __launch_bounds__(256)
k3a(const float* __restrict__ wf, const float* __restrict__ ts,
    const unsigned char* __restrict__ pad) {
    int c = blockIdx.x, b = blockIdx.y;
    int tid = threadIdx.x;
    int warp = tid >> 5, lane = tid & 31;
    int t0 = c * CROWS;

    __shared__ float s_lam[CROWS];
    __shared__ float s_valid[CROWS];
    __shared__ float s_m[8], s_Z[8], s_S[8];
    __shared__ __align__(16) float s_yp[8*Dsz];

    float tmaxv = g_tmax[b];
    if (tid < CROWS) {
        float v = pad[b*Tsz + t0 + tid] ? 0.f : 1.f;
        float dt = fmaxf(tmaxv - ts[b*Tsz + t0 + tid], 0.f) * (1.f/86400.f);
        s_lam[tid] = __expf(-0.5f*dt) * v;
        s_valid[tid] = v;
    }
    __syncthreads();

    const float4* u4 = (const float4*)(g_u + (size_t)b*Dsz);
    float4 ua = u4[lane], ub = u4[lane + 32];
    const float4* wf4 = (const float4*)(wf + (size_t)b*Tsz*Dsz + (size_t)t0*Dsz);

    float m = -3.0e38f, Z = 0.f, S = 0.f;
    float4 ya = make_float4(0.f,0.f,0.f,0.f);
    float4 yb = make_float4(0.f,0.f,0.f,0.f);

    #pragma unroll 2
    for (int t = warp*2; t < CROWS; t += 16) {
        float4 wa0 = wf4[t*64 + lane];
        float4 wb0 = wf4[t*64 + 32 + lane];
        float4 wa1 = wf4[(t+1)*64 + lane];
        float4 wb1 = wf4[(t+1)*64 + 32 + lane];
        float d0 = wa0.x*ua.x + wa0.y*ua.y + wa0.z*ua.z + wa0.w*ua.w
                 + wb0.x*ub.x + wb0.y*ub.y + wb0.z*ub.z + wb0.w*ub.w;
        float d1 = wa1.x*ua.x + wa1.y*ua.y + wa1.z*ua.z + wa1.w*ua.w
                 + wb1.x*ub.x + wb1.y*ub.y + wb1.z*ub.z + wb1.w*ub.w;
        #pragma unroll
        for (int o = 16; o > 0; o >>= 1) {
            d0 += __shfl_xor_sync(0xffffffffu, d0, o);
            d1 += __shfl_xor_sync(0xffffffffu, d1, o);
        }
        if (s_valid[t] != 0.f) {
            float s  = d0 * 0.0625f;
            float nm = fmaxf(m, s);
            float sc = __expf(m - nm);
            float e  = __expf(s - nm);
            float g  = s_lam[t] * e;
            Z = Z*sc + e;
            S = S*sc + g;
            ya.x = fmaf(ya.x, sc, g*wa0.x); ya.y = fmaf(ya.y, sc, g*wa0.y);
            ya.z = fmaf(ya.z, sc, g*wa0.z); ya.w = fmaf(ya.w, sc, g*wa0.w);
            yb.x = fmaf(yb.x, sc, g*wb0.x); yb.y = fmaf(yb.y, sc, g*wb0.y);
            yb.z = fmaf(yb.z, sc, g*wb0.z); yb.w = fmaf(yb.w, sc, g*wb0.w);
            m = nm;
        }
        if (s_valid[t+1] != 0.f) {
            float s  = d1 * 0.0625f;
            float nm = fmaxf(m, s);
            float sc = __expf(m - nm);
            float e  = __expf(s - nm);
            float g  = s_lam[t+1] * e;
            Z = Z*sc + e;
            S = S*sc + g;
            ya.x = fmaf(ya.x, sc, g*wa1.x); ya.y = fmaf(ya.y, sc, g*wa1.y);
            ya.z = fmaf(ya.z, sc, g*wa1.z); ya.w = fmaf(ya.w, sc, g*wa1.w);
            yb.x = fmaf(yb.x, sc, g*wb1.x); yb.y = fmaf(yb.y, sc, g*wb1.y);
            yb.z = fmaf(yb.z, sc, g*wb1.z); yb.w = fmaf(yb.w, sc, g*wb1.w);
            m = nm;
        }
    }

    if (lane == 0) s_m[warp] = m;
    __syncthreads();
    float M = s_m[0];
    #pragma unroll
    for (int w = 1; w < 8; w++) M = fmaxf(M, s_m[w]);
    float scw = __expf(m - M);
    if (lane == 0) { s_Z[warp] = Z*scw; s_S[warp] = S*scw; }
    float4* syp4 = (float4*)s_yp;
    syp4[warp*64 + lane]      = make_float4(ya.x*scw, ya.y*scw, ya.z*scw, ya.w*scw);
    syp4[warp*64 + 32 + lane] = make_float4(yb.x*scw, yb.y*scw, yb.z*scw, yb.w*scw);
    __syncthreads();

    int bc = b*NC + c;
    {
        float yv = 0.f;
        #pragma unroll
        for (int w = 0; w < 8; w++) yv += s_yp[w*Dsz + tid];
        g_ypart[(size_t)bc*Dsz + tid] = yv;
    }
    if (tid == 0) {
        float Zt = 0.f, St = 0.f;
        #pragma unroll
        for (int w = 0; w < 8; w++) { Zt += s_Z[w]; St += s_S[w]; }
        g_m4[bc] = M; g_Z4[bc] = Zt; g_S4[bc] = St;
    }
}

// ---------------- K4: combine y + L = y@WV^T + epilogue (2 b per block, grid 256) ----------------
__global__ void __launch_bounds__(256)
k4(const float* __restrict__ WV, const float* __restrict__ prevL,
   const float* __restrict__ prevM, const float* __restrict__ clsw,
   const float* __restrict__ clsb, float* __restrict__ out) {
    int b0 = blockIdx.x * 2, tid = threadIdx.x;
    int warp = tid >> 5, lane = tid & 31;
    __shared__ __align__(16) float s_yf[2][Dsz];
    __shared__ __align__(16) float s_L[2][Dsz];
    __shared__ float s_w1[2][8], s_w2[2][8];

    #pragma unroll
    for (int g = 0; g < 2; g++) {
        int b = b0 + g;
        float m0 = g_m4[b*NC+0], m1 = g_m4[b*NC+1], m2 = g_m4[b*NC+2], m3 = g_m4[b*NC+3];
        float M = fmaxf(fmaxf(m0, m1), fmaxf(m2, m3));
        float c0 = __expf(m0 - M), c1 = __expf(m1 - M), c2 = __expf(m2 - M), c3 = __expf(m3 - M);
        float Zt = g_Z4[b*NC+0]*c0 + g_Z4[b*NC+1]*c1 + g_Z4[b*NC+2]*c2 + g_Z4[b*NC+3]*c3;
        float St = g_S4[b*NC+0]*c0 + g_S4[b*NC+1]*c1 + g_S4[b*NC+2]*c2 + g_S4[b*NC+3]*c3;
        float yv = g_ypart[(size_t)(b*NC+0)*Dsz+tid]*c0 + g_ypart[(size_t)(b*NC+1)*Dsz+tid]*c1
                 + g_ypart[(size_t)(b*NC+2)*Dsz+tid]*c2 + g_ypart[(size_t)(b*NC+3)*Dsz+tid]*c3;
        float denom = St + 1e-8f*Zt;
        float inv = denom > 0.f ? 1.f/denom : 0.f;
        s_yf[g][tid] = yv * inv;
    }
    __syncthreads();

    // GEMM: warp-per-row, 4 rows in flight (8 LDG.128 outstanding), 2 b reuse
    {
        const float4* y0 = (const float4*)s_yf[0];
        const float4* y1 = (const float4*)s_yf[1];
        float4 y0A = y0[lane*2], y0B = y0[lane*2+1];
        float4 y1A = y1[lane*2], y1B = y1[lane*2+1];
        #pragma unroll 2
        for (int i = 0; i < 32; i += 4) {
            float4 wA[4], wB[4];
            #pragma unroll
            for (int j = 0; j < 4; j++) {
                const float4* wr = (const float4*)(WV + (size_t)(warp*32 + i + j)*Dsz);
                wA[j] = wr[lane*2]; wB[j] = wr[lane*2+1];
            }
            float d[8];
            #pragma unroll
            for (int j = 0; j < 4; j++) {
                d[j]   = wA[j].x*y0A.x + wA[j].y*y0A.y + wA[j].z*y0A.z + wA[j].w*y0A.w
                       + wB[j].x*y0B.x + wB[j].y*y0B.y + wB[j].z*y0B.z + wB[j].w*y0B.w;
                d[4+j] = wA[j].x*y1A.x + wA[j].y*y1A.y + wA[j].z*y1A.z + wA[j].w*y1A.w
                       + wB[j].x*y1B.x + wB[j].y*y1B.y + wB[j].z*y1B.z + wB[j].w*y1B.w;
            }
            #pragma unroll
            for (int o = 16; o > 0; o >>= 1) {
                #pragma unroll
                for (int k = 0; k < 8; k++) d[k] += __shfl_xor_sync(0xffffffffu, d[k], o);
            }
            if (lane == 0) {
                #pragma unroll
                for (int j = 0; j < 4; j++) {
                    s_L[0][warp*32 + i + j] = d[j];
                    s_L[1][warp*32 + i + j] = d[4+j];
                }
            }
        }
    }
    __syncthreads();

    float cw1 = clsw[tid], cw2 = clsw[Dsz + tid];
    float Lg[2], dlg[2];
    #pragma unroll
    for (int g = 0; g < 2; g++) {
        int b = b0 + g;
        float L  = s_L[g][tid];
        float dl = L - prevL[(size_t)b*Dsz + tid];
        Lg[g] = L; dlg[g] = dl;
        float r1 = dl*dl;
        float r2 = fmaf(L, cw1, dl*cw2);
        #pragma unroll
        for (int o = 16; o > 0; o >>= 1) {
            r1 += __shfl_xor_sync(0xffffffffu, r1, o);
            r2 += __shfl_xor_sync(0xffffffffu, r2, o);
        }
        if (lane == 0) { s_w1[g][warp] = r1; s_w2[g][warp] = r2; }
    }
    __syncthreads();
    #pragma unroll
    for (int g = 0; g < 2; g++) {
        int b = b0 + g;
        size_t te = (size_t)OFF_TE + (size_t)b*513;
        out[te + tid]       = Lg[g];
        out[te + 256 + tid] = dlg[g];
        out[OFF_L + (size_t)b*Dsz + tid] = Lg[g];
        if (tid == 0) {
            float R1 = 0.f, R2 = 0.f;
            #pragma unroll
            for (int w = 0; w < 8; w++) { R1 += s_w1[g][w]; R2 += s_w2[g][w]; }
            float Mt = 0.9f*prevM[b] + 0.1f*sqrtf(R1);
            out[OFF_M + b] = Mt;
            out[te + 512]  = Mt;
            out[b] = R2 + Mt*clsw[2*Dsz] + clsb[0];
        }
    }
}

extern "C" void kernel_launch(void* const* d_in, const int* in_sizes, int n_in,
                              void* d_out, int out_size) {
    const float*         wf    = (const float*)d_in[0];
    const float*         ts    = (const float*)d_in[1];
    const float*         prevL = (const float*)d_in[2];
    const float*         prevM = (const float*)d_in[3];
    const unsigned char* pad   = (const unsigned char*)d_in[4];
    const float*         WQ    = (const float*)d_in[5];
    const float*         WK    = (const float*)d_in[6];
    const float*         WV    = (const float*)d_in[7];
    const float*         clsw  = (const float*)d_in[8];
    const float*         clsb  = (const float*)d_in[9];
    float* out = (float*)d_out;

    k1a <<<dim3(NC, Bsz), 256>>>(wf, ts, pad);
    k_qu<<<Bsz/4, 256>>>(WQ, WK);
    k3a <<<dim3(NC, Bsz), 256>>>(wf, ts, pad);
    k4  <<<Bsz/2, 256>>>(WV, prevL, prevM, clsw, clsb, out);
}